// round 15
// baseline (speedup 1.0000x reference)
#include <cuda_runtime.h>
#include <cuda_bf16.h>
#include <cstddef>

// Problem constants
#define B_SZ    16
#define S_SZ    16
#define H_SZ    16
#define HD      64
#define D_MODEL 1024
#define PAST    4096
#define L_TOT   4112
#define M_ROWS  256
#define NSPLIT  16
#define TILE    32
#define KSPLIT  4

// Output layout offsets (floats): y | k | v
#define OUT_Y_OFF 0
#define OUT_K_OFF (256*1024)
#define OUT_V_OFF (OUT_K_OFF + 256*4112*64)

// cp.async helpers
__device__ __forceinline__ unsigned smem_u32(const void* p) {
    return (unsigned)__cvta_generic_to_shared(p);
}
#define CP_ASYNC16(dst_u32, src_ptr) \
    asm volatile("cp.async.cg.shared.global [%0], [%1], 16;\n" \
                 :: "r"(dst_u32), "l"(src_ptr))
#define CP_COMMIT() asm volatile("cp.async.commit_group;\n" ::)
#define CP_WAIT3()  asm volatile("cp.async.wait_group 3;\n" ::)
#define CP_WAIT1()  asm volatile("cp.async.wait_group 1;\n" ::)
#define CP_WAIT0()  asm volatile("cp.async.wait_group 0;\n" ::)

// Scratch (device globals; no allocations allowed)
__device__ float g_qkv [M_ROWS * 3 * D_MODEL];            // [256, 3072]
__device__ float g_obuf[M_ROWS * D_MODEL];                // [256, 1024]
__device__ float g_part[KSPLIT * M_ROWS * 3 * D_MODEL];   // split-K partials
__device__ float g_po  [256 * NSPLIT * 16 * 64];
__device__ float g_pm  [256 * NSPLIT * 16];
__device__ float g_pl  [256 * NSPLIT * 16];

// ---- tf32 helpers --------------------------------------------------------
__device__ __forceinline__ unsigned f2tf(float x) {
    unsigned r; asm("cvt.rna.tf32.f32 %0, %1;" : "=r"(r) : "f"(x)); return r;
}
__device__ __forceinline__ void tf_split(float x, unsigned& hi, unsigned& lo) {
    hi = f2tf(x);
    lo = f2tf(x - __uint_as_float(hi));
}
__device__ __forceinline__ void mma_tf32(float& c0, float& c1, float& c2, float& c3,
                                         unsigned a0, unsigned a1, unsigned a2, unsigned a3,
                                         unsigned b0, unsigned b1) {
    asm volatile(
        "mma.sync.aligned.m16n8k8.row.col.f32.tf32.tf32.f32 "
        "{%0,%1,%2,%3}, {%4,%5,%6,%7}, {%8,%9}, {%0,%1,%2,%3};\n"
        : "+f"(c0), "+f"(c1), "+f"(c2), "+f"(c3)
        : "r"(a0), "r"(a1), "r"(a2), "r"(a3), "r"(b0), "r"(b1));
}

// ---------------------------------------------------------------------------
// Split-K tensor-core GEMM (3xTF32), cp.async 4-stage pipeline.
// If Yred == nullptr: partials -> P[(kz*M + row)*N + n].
// Else: RED (atomicAdd) into Yred; kz==0 block adds bias.
// ---------------------------------------------------------------------------
__global__ __launch_bounds__(256)
void gemm_tf32_split_kernel(const float* __restrict__ A, const float* __restrict__ W,
                            float* __restrict__ P, int N, int K,
                            float* __restrict__ Yred, const float* __restrict__ bias) {
    __shared__ __align__(16) float As[4][64][20];
    __shared__ __align__(16) float Bs[4][64][20];

    const int tid = threadIdx.x;
    const int w   = tid >> 5;
    const int L   = tid & 31;
    const int lr4 = L >> 2;
    const int lc4 = L & 3;
    const int mf  = w >> 1;
    const int nh  = w & 1;

    const int m0 = blockIdx.y * 64;
    const int n0 = blockIdx.x * 64;
    const int kz = blockIdx.z;
    const int kbase = kz * (K / KSPLIT);

    const int srow = tid >> 2;
    const int sch  = (tid & 3) * 4;

    float acc[4][4];
    #pragma unroll
    for (int i = 0; i < 4; i++)
        #pragma unroll
        for (int j = 0; j < 4; j++) acc[i][j] = 0.f;

    const int mbase = mf * 16;
    const int nbase = nh * 32;
    const int niter = (K / KSPLIT) / 16;   // 16

    #pragma unroll
    for (int p = 0; p < 3; p++) {
        CP_ASYNC16(smem_u32(&As[p][srow][sch]),
                   &A[(size_t)(m0 + srow) * K + kbase + p * 16 + sch]);
        CP_ASYNC16(smem_u32(&Bs[p][srow][sch]),
                   &W[(size_t)(n0 + srow) * K + kbase + p * 16 + sch]);
        CP_COMMIT();
    }

    for (int t = 0; t < niter; t++) {
        const int bb = t & 3;

        if (t + 3 < niter) {
            const int k1 = kbase + (t + 3) * 16;
            const int pb = (t + 3) & 3;
            CP_ASYNC16(smem_u32(&As[pb][srow][sch]),
                       &A[(size_t)(m0 + srow) * K + k1 + sch]);
            CP_ASYNC16(smem_u32(&Bs[pb][srow][sch]),
                       &W[(size_t)(n0 + srow) * K + k1 + sch]);
        }
        CP_COMMIT();
        CP_WAIT3();
        __syncthreads();

        #pragma unroll
        for (int ks = 0; ks < 2; ks++) {
            const int kk = ks * 8;
            float af0 = As[bb][mbase + lr4    ][kk + lc4];
            float af1 = As[bb][mbase + lr4 + 8][kk + lc4];
            float af2 = As[bb][mbase + lr4    ][kk + 4 + lc4];
            float af3 = As[bb][mbase + lr4 + 8][kk + 4 + lc4];
            unsigned ah0, al0, ah1, al1, ah2, al2, ah3, al3;
            tf_split(af0, ah0, al0);
            tf_split(af1, ah1, al1);
            tf_split(af2, ah2, al2);
            tf_split(af3, ah3, al3);

            #pragma unroll
            for (int nf = 0; nf < 4; nf++) {
                const int nn = nbase + nf * 8 + lr4;
                float bf0 = Bs[bb][nn][kk + lc4];
                float bf1 = Bs[bb][nn][kk + 4 + lc4];
                unsigned bh0, bl0, bh1, bl1;
                tf_split(bf0, bh0, bl0);
                tf_split(bf1, bh1, bl1);
                mma_tf32(acc[nf][0], acc[nf][1], acc[nf][2], acc[nf][3],
                         ah0, ah1, ah2, ah3, bh0, bh1);
                mma_tf32(acc[nf][0], acc[nf][1], acc[nf][2], acc[nf][3],
                         ah0, ah1, ah2, ah3, bl0, bl1);
                mma_tf32(acc[nf][0], acc[nf][1], acc[nf][2], acc[nf][3],
                         al0, al1, al2, al3, bh0, bh1);
            }
        }
        __syncthreads();
    }

    const int row0 = m0 + mbase + lr4;
    if (Yred == nullptr) {
        const size_t pb0 = (size_t)kz * M_ROWS;
        #pragma unroll
        for (int nf = 0; nf < 4; nf++) {
            const int n = n0 + nbase + nf * 8 + lc4 * 2;
            *(float2*)&P[(pb0 + row0) * N + n]     = make_float2(acc[nf][0], acc[nf][1]);
            *(float2*)&P[(pb0 + row0 + 8) * N + n] = make_float2(acc[nf][2], acc[nf][3]);
        }
    } else {
        #pragma unroll
        for (int nf = 0; nf < 4; nf++) {
            const int n = n0 + nbase + nf * 8 + lc4 * 2;
            float v00 = acc[nf][0], v01 = acc[nf][1];
            float v10 = acc[nf][2], v11 = acc[nf][3];
            if (kz == 0) {
                float2 bb2 = *(const float2*)&bias[n];
                v00 += bb2.x; v01 += bb2.y;
                v10 += bb2.x; v11 += bb2.y;
            }
            atomicAdd(&Yred[(size_t)row0 * N + n],       v00);
            atomicAdd(&Yred[(size_t)row0 * N + n + 1],   v01);
            atomicAdd(&Yred[(size_t)(row0 + 8) * N + n],     v10);
            atomicAdd(&Yred[(size_t)(row0 + 8) * N + n + 1], v11);
        }
    }
}

// ---------------------------------------------------------------------------
// QKV reduce: sum 4 split-K partials + bias -> g_qkv; scatter new K/V rows;
// spare threads zero out_y for the RED epilogue.
// ---------------------------------------------------------------------------
__global__ __launch_bounds__(256)
void qkv_reduce_kernel(const float* __restrict__ bias,
                       float* __restrict__ sK, float* __restrict__ sV,
                       float* __restrict__ Y) {
    const unsigned idx = blockIdx.x * 256u + threadIdx.x;   // < 196608

    if (idx < 65536u)
        *(float4*)&Y[idx * 4] = make_float4(0.f, 0.f, 0.f, 0.f);

    const unsigned row = idx / 768u;
    const unsigned c4  = idx % 768u;
    const unsigned col = c4 * 4;
    const size_t o = (size_t)row * 3072 + col;

    float4 s = *(const float4*)&g_part[o];
    #pragma unroll
    for (int kz = 1; kz < KSPLIT; kz++) {
        float4 p = *(const float4*)&g_part[(size_t)kz * (M_ROWS * 3072) + o];
        s.x += p.x; s.y += p.y; s.z += p.z; s.w += p.w;
    }
    float4 bb = *(const float4*)&bias[col];
    s.x += bb.x; s.y += bb.y; s.z += bb.z; s.w += bb.w;
    *(float4*)&g_qkv[o] = s;

    if (col >= 1024) {
        const unsigned tt = (col >= 2048) ? (col - 2048) : (col - 1024);
        float* dst = (col >= 2048) ? sV : sK;
        const unsigned hh = tt >> 6, dd = tt & 63u;
        const unsigned bq = row >> 4, sq = row & 15u;
        const size_t doff = ((size_t)(bq * 16 + hh) * L_TOT + PAST + sq) * 64 + dd;
        *(float4*)&dst[doff] = s;
    }
}

// ---------------------------------------------------------------------------
// Fused attention + cache copy-out, split-KV x16, 3xTF32 tensor cores,
// cp.async double-buffered 32-row tiles, warp-specialized copy-out.
// Single fp32 q buffer (hi/lo split on the fly) -> smem ~40.7KB -> 5 blk/SM.
// ---------------------------------------------------------------------------
__global__ __launch_bounds__(256, 5)
void attn_split_kernel(const float* __restrict__ cache_k,
                       const float* __restrict__ cache_v,
                       float* __restrict__ out_k,
                       float* __restrict__ out_v) {
    __shared__ float qs[16][68];
    __shared__ __align__(16) float kt[2][TILE][68];
    __shared__ __align__(16) float vt[2][TILE][68];
    __shared__ float ptT[16][36];
    __shared__ float m_run[16], l_run[16], fac_s[16];

    const int tid   = threadIdx.x;
    const int bh    = blockIdx.x >> 4;
    const int split = blockIdx.x & 15;
    const int b = bh >> 4, h = bh & 15;

    const int w   = tid >> 5;
    const int L   = tid & 31;
    const int lr4 = L >> 2;
    const int lc4 = L & 3;

    // ---- load q, scale by 1/8 (single fp32 buffer) ----
    {
        const int q = tid >> 4, c4 = tid & 15;
        float4 qv = *(const float4*)&g_qkv[(size_t)(b * 16 + q) * 3072 + h * 64 + c4 * 4];
        qs[q][c4 * 4 + 0] = qv.x * 0.125f;
        qs[q][c4 * 4 + 1] = qv.y * 0.125f;
        qs[q][c4 * 4 + 2] = qv.z * 0.125f;
        qs[q][c4 * 4 + 3] = qv.w * 0.125f;
    }
    if (tid < 16) { m_run[tid] = -1e30f; l_run[tid] = 0.0f; }

    const int chunk0 = split * 256;
    const int nrows  = (split == 15) ? 272 : 256;
    const int ntiles = (split == 15) ? 9 : 8;
    const size_t cbase = (size_t)bh * (PAST * 64);
    const size_t obase = (size_t)bh * (L_TOT * 64);

    const int sr = tid >> 4;
    const int sc = tid & 15;

    const int pq = tid >> 4;
    const int dc = tid & 15;

    float oc0 = 0.f, oc1 = 0.f, oc2 = 0.f, oc3 = 0.f;

    auto stage = [&](int t, int bb) {
        const int l0 = chunk0 + t * TILE;
        const int rows = min(TILE, chunk0 + nrows - l0);
        #pragma unroll
        for (int i = 0; i < 2; i++) {
            const int r = sr + i * 16;
            if (r < rows) {
                const int gl = l0 + r;
                const size_t off = (size_t)gl * 64 + sc * 4;
                const float* ksrc = (gl < PAST) ? (cache_k + cbase + off)
                                                : (out_k + obase + off);
                const float* vsrc = (gl < PAST) ? (cache_v + cbase + off)
                                                : (out_v + obase + off);
                CP_ASYNC16(smem_u32(&kt[bb][r][sc * 4]), ksrc);
                CP_ASYNC16(smem_u32(&vt[bb][r][sc * 4]), vsrc);
            }
        }
    };

    stage(0, 0);
    CP_COMMIT();

    for (int t = 0; t < ntiles; t++) {
        const int bb   = t & 1;
        const int l0   = chunk0 + t * TILE;
        const int rows = min(TILE, chunk0 + nrows - l0);

        __syncthreads();

        if (t + 1 < ntiles) {
            stage(t + 1, bb ^ 1);
            CP_COMMIT();
            CP_WAIT1();
        } else {
            CP_WAIT0();
        }
        __syncthreads();

        if (w < 4) {
            // ---- scores via 3xTF32 mma (q split on the fly) ----
            float c0 = 0.f, c1 = 0.f, c2 = 0.f, c3 = 0.f;
            #pragma unroll
            for (int ks = 0; ks < 8; ks++) {
                const int k0 = ks * 8;
                float qf0 = qs[lr4    ][k0 + lc4];
                float qf1 = qs[lr4 + 8][k0 + lc4];
                float qf2 = qs[lr4    ][k0 + 4 + lc4];
                float qf3 = qs[lr4 + 8][k0 + 4 + lc4];
                unsigned ah0, al0, ah1, al1, ah2, al2, ah3, al3;
                tf_split(qf0, ah0, al0);
                tf_split(qf1, ah1, al1);
                tf_split(qf2, ah2, al2);
                tf_split(qf3, ah3, al3);
                float b0f = kt[bb][w * 8 + lr4][k0 + lc4];
                float b1f = kt[bb][w * 8 + lr4][k0 + 4 + lc4];
                unsigned bh0, bl0, bh1, bl1;
                tf_split(b0f, bh0, bl0);
                tf_split(b1f, bh1, bl1);
                mma_tf32(c0, c1, c2, c3, ah0, ah1, ah2, ah3, bh0, bh1);
                mma_tf32(c0, c1, c2, c3, ah0, ah1, ah2, ah3, bl0, bl1);
                mma_tf32(c0, c1, c2, c3, al0, al1, al2, al3, bh0, bh1);
            }
            const int n = w * 8 + lc4 * 2;
            ptT[lr4    ][n    ] = (n     < rows) ? c0 : -1e30f;
            ptT[lr4    ][n + 1] = (n + 1 < rows) ? c1 : -1e30f;
            ptT[lr4 + 8][n    ] = (n     < rows) ? c2 : -1e30f;
            ptT[lr4 + 8][n + 1] = (n + 1 < rows) ? c3 : -1e30f;
        } else {
            const int wtid = tid - 128;
            const int cr = wtid >> 4;
            const int cc = wtid & 15;
            #pragma unroll
            for (int j = 0; j < 4; j++) {
                const int r = cr + j * 8;
                const int gl = l0 + r;
                if (r < rows && gl < PAST) {
                    const size_t off = (size_t)gl * 64 + cc * 4;
                    *(float4*)&out_k[obase + off] = *(const float4*)&kt[bb][r][cc * 4];
                    *(float4*)&out_v[obase + off] = *(const float4*)&vt[bb][r][cc * 4];
                }
            }
        }
        __syncthreads();

        {
            float2 p = *(const float2*)&ptT[pq][dc * 2];
            float mt = fmaxf(p.x, p.y);
            #pragma unroll
            for (int s = 8; s >= 1; s >>= 1)
                mt = fmaxf(mt, __shfl_xor_sync(0xffffffffu, mt, s, 16));
            const float mo = m_run[pq];
            const float mn = fmaxf(mo, mt);
            const float fc = __expf(mo - mn);
            p.x = __expf(p.x - mn);
            p.y = __expf(p.y - mn);
            *(float2*)&ptT[pq][dc * 2] = p;
            float ss = p.x + p.y;
            #pragma unroll
            for (int s = 8; s >= 1; s >>= 1)
                ss += __shfl_xor_sync(0xffffffffu, ss, s, 16);
            if (dc == 0) {
                m_run[pq] = mn;
                fac_s[pq] = fc;
                l_run[pq] = l_run[pq] * fc + ss;
            }
        }
        __syncthreads();

        {
            const float f0 = fac_s[lr4];
            const float f1 = fac_s[lr4 + 8];
            oc0 *= f0; oc1 *= f0; oc2 *= f1; oc3 *= f1;

            #pragma unroll
            for (int ks = 0; ks < 4; ks++) {
                const int k0 = ks * 8;
                float af0 = ptT[lr4    ][k0 + lc4];
                float af1 = ptT[lr4 + 8][k0 + lc4];
                float af2 = ptT[lr4    ][k0 + 4 + lc4];
                float af3 = ptT[lr4 + 8][k0 + 4 + lc4];
                unsigned ah0, al0, ah1, al1, ah2, al2, ah3, al3;
                tf_split(af0, ah0, al0);
                tf_split(af1, ah1, al1);
                tf_split(af2, ah2, al2);
                tf_split(af3, ah3, al3);
                float b0f = vt[bb][k0 + lc4    ][w * 8 + lr4];
                float b1f = vt[bb][k0 + 4 + lc4][w * 8 + lr4];
                unsigned bh0, bl0, bh1, bl1;
                tf_split(b0f, bh0, bl0);
                tf_split(b1f, bh1, bl1);
                mma_tf32(oc0, oc1, oc2, oc3, ah0, ah1, ah2, ah3, bh0, bh1);
                mma_tf32(oc0, oc1, oc2, oc3, ah0, ah1, ah2, ah3, bl0, bl1);
                mma_tf32(oc0, oc1, oc2, oc3, al0, al1, al2, al3, bh0, bh1);
            }
        }
    }

    {
        const size_t pbase = (size_t)blockIdx.x * 1024;
        const int d = w * 8 + lc4 * 2;
        *(float2*)&g_po[pbase + lr4       * 64 + d] = make_float2(oc0, oc1);
        *(float2*)&g_po[pbase + (lr4 + 8) * 64 + d] = make_float2(oc2, oc3);
    }
    if (tid < 16) {
        g_pm[blockIdx.x * 16 + tid] = m_run[tid];
        g_pl[blockIdx.x * 16 + tid] = l_run[tid];
    }
}

// ---------------------------------------------------------------------------
// Combine split partials -> g_obuf [B,S,H*hd]
// ---------------------------------------------------------------------------
__global__ __launch_bounds__(256)
void attn_reduce_kernel() {
    const int bh = blockIdx.x;
    const int tid = threadIdx.x;
    const int pq = tid >> 4, dc = tid & 15;
    const int base = bh * NSPLIT;

    float mm = -1e30f;
    #pragma unroll
    for (int s = 0; s < NSPLIT; s++)
        mm = fmaxf(mm, g_pm[(base + s) * 16 + pq]);

    float4 acc = make_float4(0.f, 0.f, 0.f, 0.f);
    float l = 0.f;
    #pragma unroll
    for (int s = 0; s < NSPLIT; s++) {
        float w = __expf(g_pm[(base + s) * 16 + pq] - mm);
        float4 o = *(const float4*)&g_po[(size_t)(base + s) * 1024 + pq * 64 + dc * 4];
        acc.x += w * o.x; acc.y += w * o.y;
        acc.z += w * o.z; acc.w += w * o.w;
        l += w * g_pl[(base + s) * 16 + pq];
    }
    float inv = 1.0f / l;
    const int b = bh >> 4, h = bh & 15;
    float4 r = make_float4(acc.x * inv, acc.y * inv, acc.z * inv, acc.w * inv);
    *(float4*)&g_obuf[(size_t)(b * 16 + pq) * D_MODEL + h * 64 + dc * 4] = r;
}

// ---------------------------------------------------------------------------
extern "C" void kernel_launch(void* const* d_in, const int* in_sizes, int n_in,
                              void* d_out, int out_size) {
    const float* x       = (const float*)d_in[0];
    const float* cache_k = (const float*)d_in[1];
    const float* cache_v = (const float*)d_in[2];
    const float* qkv_w   = (const float*)d_in[3];
    const float* qkv_b   = (const float*)d_in[4];
    const float* out_w   = (const float*)d_in[5];
    const float* out_b   = (const float*)d_in[6];

    float* out   = (float*)d_out;
    float* out_y = out + OUT_Y_OFF;
    float* out_k = out + OUT_K_OFF;
    float* out_v = out + OUT_V_OFF;

    float *obuf_p = nullptr, *part_p = nullptr;
    cudaGetSymbolAddress((void**)&obuf_p, g_obuf);
    cudaGetSymbolAddress((void**)&part_p, g_part);

    // 1) QKV projection, split-K x4 -> partials
    gemm_tf32_split_kernel<<<dim3(3072 / 64, M_ROWS / 64, KSPLIT), 256>>>(
        x, qkv_w, part_p, 3072, D_MODEL, nullptr, nullptr);

    // 2) Reduce partials + bias -> g_qkv; scatter new K/V; zero out_y
    qkv_reduce_kernel<<<768, 256>>>(qkv_b, out_k, out_v, out_y);

    // 3) Fused attention + cache copy-out (split-KV x16, TC + cp.async, 5 blk/SM)
    attn_split_kernel<<<B_SZ * H_SZ * NSPLIT, 256>>>(cache_k, cache_v, out_k, out_v);

    // 4) Combine splits -> g_obuf
    attn_reduce_kernel<<<B_SZ * H_SZ, 256>>>();

    // 5) Output projection, split-K x4, RED directly into out_y (+bias)
    gemm_tf32_split_kernel<<<dim3(D_MODEL / 64, M_ROWS / 64, KSPLIT), 256>>>(
        obuf_p, out_w, nullptr, D_MODEL, D_MODEL, out_y, out_b);
}

// round 16
// speedup vs baseline: 1.0161x; 1.0161x over previous
#include <cuda_runtime.h>
#include <cuda_bf16.h>
#include <cstddef>

// Problem constants
#define B_SZ    16
#define S_SZ    16
#define H_SZ    16
#define HD      64
#define D_MODEL 1024
#define PAST    4096
#define L_TOT   4112
#define M_ROWS  256
#define NSPLIT  16
#define TILE    32
#define KSPLIT  4

// Output layout offsets (floats): y | k | v
#define OUT_Y_OFF 0
#define OUT_K_OFF (256*1024)
#define OUT_V_OFF (OUT_K_OFF + 256*4112*64)

// cp.async helpers
__device__ __forceinline__ unsigned smem_u32(const void* p) {
    return (unsigned)__cvta_generic_to_shared(p);
}
#define CP_ASYNC16(dst_u32, src_ptr) \
    asm volatile("cp.async.cg.shared.global [%0], [%1], 16;\n" \
                 :: "r"(dst_u32), "l"(src_ptr))
#define CP_COMMIT() asm volatile("cp.async.commit_group;\n" ::)
#define CP_WAIT3()  asm volatile("cp.async.wait_group 3;\n" ::)
#define CP_WAIT1()  asm volatile("cp.async.wait_group 1;\n" ::)
#define CP_WAIT0()  asm volatile("cp.async.wait_group 0;\n" ::)

// Scratch (device globals; no allocations allowed)
__device__ float g_qkv_unused[1];                          // (kept for ABI sanity)
__device__ float g_obuf[M_ROWS * D_MODEL];                 // [256, 1024]
__device__ float g_part[KSPLIT * M_ROWS * 3 * D_MODEL];    // split-K partials
__device__ float g_po  [256 * NSPLIT * 16 * 64];
__device__ float g_pm  [256 * NSPLIT * 16];
__device__ float g_pl  [256 * NSPLIT * 16];

// ---- tf32 helpers --------------------------------------------------------
__device__ __forceinline__ unsigned f2tf(float x) {
    unsigned r; asm("cvt.rna.tf32.f32 %0, %1;" : "=r"(r) : "f"(x)); return r;
}
__device__ __forceinline__ void tf_split(float x, unsigned& hi, unsigned& lo) {
    hi = f2tf(x);
    lo = f2tf(x - __uint_as_float(hi));
}
__device__ __forceinline__ void mma_tf32(float& c0, float& c1, float& c2, float& c3,
                                         unsigned a0, unsigned a1, unsigned a2, unsigned a3,
                                         unsigned b0, unsigned b1) {
    asm volatile(
        "mma.sync.aligned.m16n8k8.row.col.f32.tf32.tf32.f32 "
        "{%0,%1,%2,%3}, {%4,%5,%6,%7}, {%8,%9}, {%0,%1,%2,%3};\n"
        : "+f"(c0), "+f"(c1), "+f"(c2), "+f"(c3)
        : "r"(a0), "r"(a1), "r"(a2), "r"(a3), "r"(b0), "r"(b1));
}

// ---------------------------------------------------------------------------
// Split-K tensor-core GEMM (3xTF32), cp.async 4-stage pipeline.
// If Yred == nullptr: partials -> P[(kz*M + row)*N + n].
// Else: RED (atomicAdd) into Yred; kz==0 block adds bias.
// ---------------------------------------------------------------------------
__global__ __launch_bounds__(256)
void gemm_tf32_split_kernel(const float* __restrict__ A, const float* __restrict__ W,
                            float* __restrict__ P, int N, int K,
                            float* __restrict__ Yred, const float* __restrict__ bias) {
    __shared__ __align__(16) float As[4][64][20];
    __shared__ __align__(16) float Bs[4][64][20];

    const int tid = threadIdx.x;
    const int w   = tid >> 5;
    const int L   = tid & 31;
    const int lr4 = L >> 2;
    const int lc4 = L & 3;
    const int mf  = w >> 1;
    const int nh  = w & 1;

    const int m0 = blockIdx.y * 64;
    const int n0 = blockIdx.x * 64;
    const int kz = blockIdx.z;
    const int kbase = kz * (K / KSPLIT);

    const int srow = tid >> 2;
    const int sch  = (tid & 3) * 4;

    float acc[4][4];
    #pragma unroll
    for (int i = 0; i < 4; i++)
        #pragma unroll
        for (int j = 0; j < 4; j++) acc[i][j] = 0.f;

    const int mbase = mf * 16;
    const int nbase = nh * 32;
    const int niter = (K / KSPLIT) / 16;   // 16

    #pragma unroll
    for (int p = 0; p < 3; p++) {
        CP_ASYNC16(smem_u32(&As[p][srow][sch]),
                   &A[(size_t)(m0 + srow) * K + kbase + p * 16 + sch]);
        CP_ASYNC16(smem_u32(&Bs[p][srow][sch]),
                   &W[(size_t)(n0 + srow) * K + kbase + p * 16 + sch]);
        CP_COMMIT();
    }

    for (int t = 0; t < niter; t++) {
        const int bb = t & 3;

        if (t + 3 < niter) {
            const int k1 = kbase + (t + 3) * 16;
            const int pb = (t + 3) & 3;
            CP_ASYNC16(smem_u32(&As[pb][srow][sch]),
                       &A[(size_t)(m0 + srow) * K + k1 + sch]);
            CP_ASYNC16(smem_u32(&Bs[pb][srow][sch]),
                       &W[(size_t)(n0 + srow) * K + k1 + sch]);
        }
        CP_COMMIT();
        CP_WAIT3();
        __syncthreads();

        #pragma unroll
        for (int ks = 0; ks < 2; ks++) {
            const int kk = ks * 8;
            float af0 = As[bb][mbase + lr4    ][kk + lc4];
            float af1 = As[bb][mbase + lr4 + 8][kk + lc4];
            float af2 = As[bb][mbase + lr4    ][kk + 4 + lc4];
            float af3 = As[bb][mbase + lr4 + 8][kk + 4 + lc4];
            unsigned ah0, al0, ah1, al1, ah2, al2, ah3, al3;
            tf_split(af0, ah0, al0);
            tf_split(af1, ah1, al1);
            tf_split(af2, ah2, al2);
            tf_split(af3, ah3, al3);

            #pragma unroll
            for (int nf = 0; nf < 4; nf++) {
                const int nn = nbase + nf * 8 + lr4;
                float bf0 = Bs[bb][nn][kk + lc4];
                float bf1 = Bs[bb][nn][kk + 4 + lc4];
                unsigned bh0, bl0, bh1, bl1;
                tf_split(bf0, bh0, bl0);
                tf_split(bf1, bh1, bl1);
                mma_tf32(acc[nf][0], acc[nf][1], acc[nf][2], acc[nf][3],
                         ah0, ah1, ah2, ah3, bh0, bh1);
                mma_tf32(acc[nf][0], acc[nf][1], acc[nf][2], acc[nf][3],
                         ah0, ah1, ah2, ah3, bl0, bl1);
                mma_tf32(acc[nf][0], acc[nf][1], acc[nf][2], acc[nf][3],
                         al0, al1, al2, al3, bh0, bh1);
            }
        }
        __syncthreads();
    }

    const int row0 = m0 + mbase + lr4;
    if (Yred == nullptr) {
        const size_t pb0 = (size_t)kz * M_ROWS;
        #pragma unroll
        for (int nf = 0; nf < 4; nf++) {
            const int n = n0 + nbase + nf * 8 + lc4 * 2;
            *(float2*)&P[(pb0 + row0) * N + n]     = make_float2(acc[nf][0], acc[nf][1]);
            *(float2*)&P[(pb0 + row0 + 8) * N + n] = make_float2(acc[nf][2], acc[nf][3]);
        }
    } else {
        #pragma unroll
        for (int nf = 0; nf < 4; nf++) {
            const int n = n0 + nbase + nf * 8 + lc4 * 2;
            float v00 = acc[nf][0], v01 = acc[nf][1];
            float v10 = acc[nf][2], v11 = acc[nf][3];
            if (kz == 0) {
                float2 bb2 = *(const float2*)&bias[n];
                v00 += bb2.x; v01 += bb2.y;
                v10 += bb2.x; v11 += bb2.y;
            }
            atomicAdd(&Yred[(size_t)row0 * N + n],       v00);
            atomicAdd(&Yred[(size_t)row0 * N + n + 1],   v01);
            atomicAdd(&Yred[(size_t)(row0 + 8) * N + n],     v10);
            atomicAdd(&Yred[(size_t)(row0 + 8) * N + n + 1], v11);
        }
    }
}

// ---------------------------------------------------------------------------
// Fused attention + cache copy-out, split-KV x16, 3xTF32 tensor cores,
// cp.async double-buffered 32-row tiles, warp-specialized copy-out.
// q is reduced from the 4 QKV split-K partials + bias in-kernel; split 15
// blocks also materialize the 16 new K/V rows from partials into out_k/out_v
// before their pipeline reaches the tail tile.
// ---------------------------------------------------------------------------
__global__ __launch_bounds__(256)
void attn_split_kernel(const float* __restrict__ cache_k,
                       const float* __restrict__ cache_v,
                       float* __restrict__ out_k,
                       float* __restrict__ out_v,
                       const float* __restrict__ qkv_b) {
    __shared__ unsigned qh[16][68];
    __shared__ unsigned ql[16][68];
    __shared__ __align__(16) float kt[2][TILE][68];
    __shared__ __align__(16) float vt[2][TILE][68];
    __shared__ float ptT[16][36];
    __shared__ float m_run[16], l_run[16], fac_s[16];

    const int tid   = threadIdx.x;
    const int bh    = blockIdx.x >> 4;
    const int split = blockIdx.x & 15;
    const int b = bh >> 4, h = bh & 15;

    const int w   = tid >> 5;
    const int L   = tid & 31;
    const int lr4 = L >> 2;
    const int lc4 = L & 3;

    const size_t cbase = (size_t)bh * (PAST * 64);
    const size_t obase = (size_t)bh * (L_TOT * 64);

    // ---- q = sum of 4 split-K partials + bias, scaled, hi/lo split ----
    {
        const int q = tid >> 4, c4 = tid & 15;
        const size_t qoff = (size_t)(b * 16 + q) * 3072 + h * 64 + c4 * 4;
        float4 qv = *(const float4*)&g_part[qoff];
        #pragma unroll
        for (int kz = 1; kz < KSPLIT; kz++) {
            float4 p = *(const float4*)&g_part[(size_t)kz * (M_ROWS * 3072) + qoff];
            qv.x += p.x; qv.y += p.y; qv.z += p.z; qv.w += p.w;
        }
        float4 bb = *(const float4*)&qkv_b[h * 64 + c4 * 4];
        qv.x = (qv.x + bb.x) * 0.125f;
        qv.y = (qv.y + bb.y) * 0.125f;
        qv.z = (qv.z + bb.z) * 0.125f;
        qv.w = (qv.w + bb.w) * 0.125f;
        unsigned hi, lo;
        tf_split(qv.x, hi, lo); qh[q][c4 * 4 + 0] = hi; ql[q][c4 * 4 + 0] = lo;
        tf_split(qv.y, hi, lo); qh[q][c4 * 4 + 1] = hi; ql[q][c4 * 4 + 1] = lo;
        tf_split(qv.z, hi, lo); qh[q][c4 * 4 + 2] = hi; ql[q][c4 * 4 + 2] = lo;
        tf_split(qv.w, hi, lo); qh[q][c4 * 4 + 3] = hi; ql[q][c4 * 4 + 3] = lo;
    }

    // ---- split 15: materialize new K/V tail rows from partials ----
    if (split == 15) {
        const int s = tid >> 4, d4 = tid & 15;
        const size_t rbase = (size_t)(b * 16 + s) * 3072 + h * 64 + d4 * 4;
        float4 kv = *(const float4*)&g_part[rbase + 1024];
        float4 vv = *(const float4*)&g_part[rbase + 2048];
        #pragma unroll
        for (int kz = 1; kz < KSPLIT; kz++) {
            const size_t off = (size_t)kz * (M_ROWS * 3072) + rbase;
            float4 pk = *(const float4*)&g_part[off + 1024];
            float4 pv = *(const float4*)&g_part[off + 2048];
            kv.x += pk.x; kv.y += pk.y; kv.z += pk.z; kv.w += pk.w;
            vv.x += pv.x; vv.y += pv.y; vv.z += pv.z; vv.w += pv.w;
        }
        float4 bk = *(const float4*)&qkv_b[1024 + h * 64 + d4 * 4];
        float4 bv = *(const float4*)&qkv_b[2048 + h * 64 + d4 * 4];
        kv.x += bk.x; kv.y += bk.y; kv.z += bk.z; kv.w += bk.w;
        vv.x += bv.x; vv.y += bv.y; vv.z += bv.z; vv.w += bv.w;
        const size_t doff = obase + (size_t)(PAST + s) * 64 + d4 * 4;
        *(float4*)&out_k[doff] = kv;
        *(float4*)&out_v[doff] = vv;
    }
    if (tid < 16) { m_run[tid] = -1e30f; l_run[tid] = 0.0f; }
    __syncthreads();   // tail rows + q visible before any staging reads them

    const int chunk0 = split * 256;
    const int nrows  = (split == 15) ? 272 : 256;
    const int ntiles = (split == 15) ? 9 : 8;

    const int sr = tid >> 4;
    const int sc = tid & 15;

    const int pq = tid >> 4;
    const int dc = tid & 15;

    float oc0 = 0.f, oc1 = 0.f, oc2 = 0.f, oc3 = 0.f;

    auto stage = [&](int t, int bb) {
        const int l0 = chunk0 + t * TILE;
        const int rows = min(TILE, chunk0 + nrows - l0);
        #pragma unroll
        for (int i = 0; i < 2; i++) {
            const int r = sr + i * 16;
            if (r < rows) {
                const int gl = l0 + r;
                const size_t off = (size_t)gl * 64 + sc * 4;
                const float* ksrc = (gl < PAST) ? (cache_k + cbase + off)
                                                : (out_k + obase + off);
                const float* vsrc = (gl < PAST) ? (cache_v + cbase + off)
                                                : (out_v + obase + off);
                CP_ASYNC16(smem_u32(&kt[bb][r][sc * 4]), ksrc);
                CP_ASYNC16(smem_u32(&vt[bb][r][sc * 4]), vsrc);
            }
        }
    };

    stage(0, 0);
    CP_COMMIT();

    for (int t = 0; t < ntiles; t++) {
        const int bb   = t & 1;
        const int l0   = chunk0 + t * TILE;
        const int rows = min(TILE, chunk0 + nrows - l0);

        __syncthreads();

        if (t + 1 < ntiles) {
            stage(t + 1, bb ^ 1);
            CP_COMMIT();
            CP_WAIT1();
        } else {
            CP_WAIT0();
        }
        __syncthreads();

        if (w < 4) {
            float c0 = 0.f, c1 = 0.f, c2 = 0.f, c3 = 0.f;
            #pragma unroll
            for (int ks = 0; ks < 8; ks++) {
                const int k0 = ks * 8;
                unsigned ah0 = qh[lr4    ][k0 + lc4];
                unsigned ah1 = qh[lr4 + 8][k0 + lc4];
                unsigned ah2 = qh[lr4    ][k0 + 4 + lc4];
                unsigned ah3 = qh[lr4 + 8][k0 + 4 + lc4];
                unsigned al0 = ql[lr4    ][k0 + lc4];
                unsigned al1 = ql[lr4 + 8][k0 + lc4];
                unsigned al2 = ql[lr4    ][k0 + 4 + lc4];
                unsigned al3 = ql[lr4 + 8][k0 + 4 + lc4];
                float b0f = kt[bb][w * 8 + lr4][k0 + lc4];
                float b1f = kt[bb][w * 8 + lr4][k0 + 4 + lc4];
                unsigned bh0, bl0, bh1, bl1;
                tf_split(b0f, bh0, bl0);
                tf_split(b1f, bh1, bl1);
                mma_tf32(c0, c1, c2, c3, ah0, ah1, ah2, ah3, bh0, bh1);
                mma_tf32(c0, c1, c2, c3, ah0, ah1, ah2, ah3, bl0, bl1);
                mma_tf32(c0, c1, c2, c3, al0, al1, al2, al3, bh0, bh1);
            }
            const int n = w * 8 + lc4 * 2;
            ptT[lr4    ][n    ] = (n     < rows) ? c0 : -1e30f;
            ptT[lr4    ][n + 1] = (n + 1 < rows) ? c1 : -1e30f;
            ptT[lr4 + 8][n    ] = (n     < rows) ? c2 : -1e30f;
            ptT[lr4 + 8][n + 1] = (n + 1 < rows) ? c3 : -1e30f;
        } else {
            const int wtid = tid - 128;
            const int cr = wtid >> 4;
            const int cc = wtid & 15;
            #pragma unroll
            for (int j = 0; j < 4; j++) {
                const int r = cr + j * 8;
                const int gl = l0 + r;
                if (r < rows && gl < PAST) {
                    const size_t off = (size_t)gl * 64 + cc * 4;
                    *(float4*)&out_k[obase + off] = *(const float4*)&kt[bb][r][cc * 4];
                    *(float4*)&out_v[obase + off] = *(const float4*)&vt[bb][r][cc * 4];
                }
            }
        }
        __syncthreads();

        {
            float2 p = *(const float2*)&ptT[pq][dc * 2];
            float mt = fmaxf(p.x, p.y);
            #pragma unroll
            for (int s = 8; s >= 1; s >>= 1)
                mt = fmaxf(mt, __shfl_xor_sync(0xffffffffu, mt, s, 16));
            const float mo = m_run[pq];
            const float mn = fmaxf(mo, mt);
            const float fc = __expf(mo - mn);
            p.x = __expf(p.x - mn);
            p.y = __expf(p.y - mn);
            *(float2*)&ptT[pq][dc * 2] = p;
            float ss = p.x + p.y;
            #pragma unroll
            for (int s = 8; s >= 1; s >>= 1)
                ss += __shfl_xor_sync(0xffffffffu, ss, s, 16);
            if (dc == 0) {
                m_run[pq] = mn;
                fac_s[pq] = fc;
                l_run[pq] = l_run[pq] * fc + ss;
            }
        }
        __syncthreads();

        {
            const float f0 = fac_s[lr4];
            const float f1 = fac_s[lr4 + 8];
            oc0 *= f0; oc1 *= f0; oc2 *= f1; oc3 *= f1;

            #pragma unroll
            for (int ks = 0; ks < 4; ks++) {
                const int k0 = ks * 8;
                float af0 = ptT[lr4    ][k0 + lc4];
                float af1 = ptT[lr4 + 8][k0 + lc4];
                float af2 = ptT[lr4    ][k0 + 4 + lc4];
                float af3 = ptT[lr4 + 8][k0 + 4 + lc4];
                unsigned ah0, al0, ah1, al1, ah2, al2, ah3, al3;
                tf_split(af0, ah0, al0);
                tf_split(af1, ah1, al1);
                tf_split(af2, ah2, al2);
                tf_split(af3, ah3, al3);
                float b0f = vt[bb][k0 + lc4    ][w * 8 + lr4];
                float b1f = vt[bb][k0 + 4 + lc4][w * 8 + lr4];
                unsigned bh0, bl0, bh1, bl1;
                tf_split(b0f, bh0, bl0);
                tf_split(b1f, bh1, bl1);
                mma_tf32(oc0, oc1, oc2, oc3, ah0, ah1, ah2, ah3, bh0, bh1);
                mma_tf32(oc0, oc1, oc2, oc3, ah0, ah1, ah2, ah3, bl0, bl1);
                mma_tf32(oc0, oc1, oc2, oc3, al0, al1, al2, al3, bh0, bh1);
            }
        }
    }

    {
        const size_t pbase = (size_t)blockIdx.x * 1024;
        const int d = w * 8 + lc4 * 2;
        *(float2*)&g_po[pbase + lr4       * 64 + d] = make_float2(oc0, oc1);
        *(float2*)&g_po[pbase + (lr4 + 8) * 64 + d] = make_float2(oc2, oc3);
    }
    if (tid < 16) {
        g_pm[blockIdx.x * 16 + tid] = m_run[tid];
        g_pl[blockIdx.x * 16 + tid] = l_run[tid];
    }
}

// ---------------------------------------------------------------------------
// Combine split partials -> g_obuf; also zero out_y for the y-GEMM RED.
// ---------------------------------------------------------------------------
__global__ __launch_bounds__(256)
void attn_reduce_kernel(float* __restrict__ Y) {
    const int bh = blockIdx.x;
    const int tid = threadIdx.x;
    const int pq = tid >> 4, dc = tid & 15;
    const int base = bh * NSPLIT;

    // zero out_y: 256 blocks x 256 threads x one float4 = 262144 floats
    {
        const unsigned idx = blockIdx.x * 256u + tid;
        *(float4*)&Y[idx * 4] = make_float4(0.f, 0.f, 0.f, 0.f);
    }

    float mm = -1e30f;
    #pragma unroll
    for (int s = 0; s < NSPLIT; s++)
        mm = fmaxf(mm, g_pm[(base + s) * 16 + pq]);

    float4 acc = make_float4(0.f, 0.f, 0.f, 0.f);
    float l = 0.f;
    #pragma unroll
    for (int s = 0; s < NSPLIT; s++) {
        float w = __expf(g_pm[(base + s) * 16 + pq] - mm);
        float4 o = *(const float4*)&g_po[(size_t)(base + s) * 1024 + pq * 64 + dc * 4];
        acc.x += w * o.x; acc.y += w * o.y;
        acc.z += w * o.z; acc.w += w * o.w;
        l += w * g_pl[(base + s) * 16 + pq];
    }
    float inv = 1.0f / l;
    const int b = bh >> 4, h = bh & 15;
    float4 r = make_float4(acc.x * inv, acc.y * inv, acc.z * inv, acc.w * inv);
    *(float4*)&g_obuf[(size_t)(b * 16 + pq) * D_MODEL + h * 64 + dc * 4] = r;
}

// ---------------------------------------------------------------------------
extern "C" void kernel_launch(void* const* d_in, const int* in_sizes, int n_in,
                              void* d_out, int out_size) {
    const float* x       = (const float*)d_in[0];
    const float* cache_k = (const float*)d_in[1];
    const float* cache_v = (const float*)d_in[2];
    const float* qkv_w   = (const float*)d_in[3];
    const float* qkv_b   = (const float*)d_in[4];
    const float* out_w   = (const float*)d_in[5];
    const float* out_b   = (const float*)d_in[6];

    float* out   = (float*)d_out;
    float* out_y = out + OUT_Y_OFF;
    float* out_k = out + OUT_K_OFF;
    float* out_v = out + OUT_V_OFF;

    float *obuf_p = nullptr, *part_p = nullptr;
    cudaGetSymbolAddress((void**)&obuf_p, g_obuf);
    cudaGetSymbolAddress((void**)&part_p, g_part);

    // 1) QKV projection, split-K x4 -> partials (consumed directly by attn)
    gemm_tf32_split_kernel<<<dim3(3072 / 64, M_ROWS / 64, KSPLIT), 256>>>(
        x, qkv_w, part_p, 3072, D_MODEL, nullptr, nullptr);

    // 2) Fused attention + cache copy-out; q and new-KV tail reduced in-kernel
    attn_split_kernel<<<B_SZ * H_SZ * NSPLIT, 256>>>(
        cache_k, cache_v, out_k, out_v, qkv_b);

    // 3) Combine splits -> g_obuf; zero out_y
    attn_reduce_kernel<<<B_SZ * H_SZ, 256>>>(out_y);

    // 4) Output projection, split-K x4, RED directly into out_y (+bias)
    gemm_tf32_split_kernel<<<dim3(D_MODEL / 64, M_ROWS / 64, KSPLIT), 256>>>(
        obuf_p, out_w, nullptr, D_MODEL, D_MODEL, out_y, out_b);
}

// round 17
// speedup vs baseline: 1.0166x; 1.0006x over previous
#include <cuda_runtime.h>
#include <cuda_bf16.h>
#include <cstddef>

// Problem constants
#define B_SZ    16
#define S_SZ    16
#define H_SZ    16
#define HD      64
#define D_MODEL 1024
#define PAST    4096
#define L_TOT   4112
#define M_ROWS  256
#define NSPLIT  16
#define TILE    32
#define KSPLIT  4     // QKV projection split (attention reads 4 partials)
#define KSPLIT_Y 8    // y projection split (RED epilogue, any split works)

// Output layout offsets (floats): y | k | v
#define OUT_Y_OFF 0
#define OUT_K_OFF (256*1024)
#define OUT_V_OFF (OUT_K_OFF + 256*4112*64)

// cp.async helpers
__device__ __forceinline__ unsigned smem_u32(const void* p) {
    return (unsigned)__cvta_generic_to_shared(p);
}
#define CP_ASYNC16(dst_u32, src_ptr) \
    asm volatile("cp.async.cg.shared.global [%0], [%1], 16;\n" \
                 :: "r"(dst_u32), "l"(src_ptr))
#define CP_COMMIT() asm volatile("cp.async.commit_group;\n" ::)
#define CP_WAIT3()  asm volatile("cp.async.wait_group 3;\n" ::)
#define CP_WAIT1()  asm volatile("cp.async.wait_group 1;\n" ::)
#define CP_WAIT0()  asm volatile("cp.async.wait_group 0;\n" ::)

// Scratch (device globals; no allocations allowed)
__device__ float g_obuf[M_ROWS * D_MODEL];                 // [256, 1024]
__device__ float g_part[KSPLIT * M_ROWS * 3 * D_MODEL];    // split-K partials
__device__ float g_po  [256 * NSPLIT * 16 * 64];
__device__ float g_pm  [256 * NSPLIT * 16];
__device__ float g_pl  [256 * NSPLIT * 16];

// ---- tf32 helpers --------------------------------------------------------
__device__ __forceinline__ unsigned f2tf(float x) {
    unsigned r; asm("cvt.rna.tf32.f32 %0, %1;" : "=r"(r) : "f"(x)); return r;
}
__device__ __forceinline__ void tf_split(float x, unsigned& hi, unsigned& lo) {
    hi = f2tf(x);
    lo = f2tf(x - __uint_as_float(hi));
}
__device__ __forceinline__ void mma_tf32(float& c0, float& c1, float& c2, float& c3,
                                         unsigned a0, unsigned a1, unsigned a2, unsigned a3,
                                         unsigned b0, unsigned b1) {
    asm volatile(
        "mma.sync.aligned.m16n8k8.row.col.f32.tf32.tf32.f32 "
        "{%0,%1,%2,%3}, {%4,%5,%6,%7}, {%8,%9}, {%0,%1,%2,%3};\n"
        : "+f"(c0), "+f"(c1), "+f"(c2), "+f"(c3)
        : "r"(a0), "r"(a1), "r"(a2), "r"(a3), "r"(b0), "r"(b1));
}

// ---------------------------------------------------------------------------
// Split-K tensor-core GEMM (3xTF32), cp.async 4-stage pipeline.
// Split factor = gridDim.z. If Yred == nullptr: partials -> P.
// Else: RED (atomicAdd) into Yred; kz==0 block adds bias.
// ---------------------------------------------------------------------------
__global__ __launch_bounds__(256)
void gemm_tf32_split_kernel(const float* __restrict__ A, const float* __restrict__ W,
                            float* __restrict__ P, int N, int K,
                            float* __restrict__ Yred, const float* __restrict__ bias) {
    __shared__ __align__(16) float As[4][64][20];
    __shared__ __align__(16) float Bs[4][64][20];

    const int tid = threadIdx.x;
    const int w   = tid >> 5;
    const int L   = tid & 31;
    const int lr4 = L >> 2;
    const int lc4 = L & 3;
    const int mf  = w >> 1;
    const int nh  = w & 1;

    const int m0 = blockIdx.y * 64;
    const int n0 = blockIdx.x * 64;
    const int kz = blockIdx.z;
    const int kslab = K / gridDim.z;
    const int kbase = kz * kslab;

    const int srow = tid >> 2;
    const int sch  = (tid & 3) * 4;

    float acc[4][4];
    #pragma unroll
    for (int i = 0; i < 4; i++)
        #pragma unroll
        for (int j = 0; j < 4; j++) acc[i][j] = 0.f;

    const int mbase = mf * 16;
    const int nbase = nh * 32;
    const int niter = kslab / 16;

    #pragma unroll
    for (int p = 0; p < 3; p++) {
        if (p < niter) {
            CP_ASYNC16(smem_u32(&As[p][srow][sch]),
                       &A[(size_t)(m0 + srow) * K + kbase + p * 16 + sch]);
            CP_ASYNC16(smem_u32(&Bs[p][srow][sch]),
                       &W[(size_t)(n0 + srow) * K + kbase + p * 16 + sch]);
        }
        CP_COMMIT();
    }

    for (int t = 0; t < niter; t++) {
        const int bb = t & 3;

        if (t + 3 < niter) {
            const int k1 = kbase + (t + 3) * 16;
            const int pb = (t + 3) & 3;
            CP_ASYNC16(smem_u32(&As[pb][srow][sch]),
                       &A[(size_t)(m0 + srow) * K + k1 + sch]);
            CP_ASYNC16(smem_u32(&Bs[pb][srow][sch]),
                       &W[(size_t)(n0 + srow) * K + k1 + sch]);
        }
        CP_COMMIT();
        CP_WAIT3();
        __syncthreads();

        #pragma unroll
        for (int ks = 0; ks < 2; ks++) {
            const int kk = ks * 8;
            float af0 = As[bb][mbase + lr4    ][kk + lc4];
            float af1 = As[bb][mbase + lr4 + 8][kk + lc4];
            float af2 = As[bb][mbase + lr4    ][kk + 4 + lc4];
            float af3 = As[bb][mbase + lr4 + 8][kk + 4 + lc4];
            unsigned ah0, al0, ah1, al1, ah2, al2, ah3, al3;
            tf_split(af0, ah0, al0);
            tf_split(af1, ah1, al1);
            tf_split(af2, ah2, al2);
            tf_split(af3, ah3, al3);

            #pragma unroll
            for (int nf = 0; nf < 4; nf++) {
                const int nn = nbase + nf * 8 + lr4;
                float bf0 = Bs[bb][nn][kk + lc4];
                float bf1 = Bs[bb][nn][kk + 4 + lc4];
                unsigned bh0, bl0, bh1, bl1;
                tf_split(bf0, bh0, bl0);
                tf_split(bf1, bh1, bl1);
                mma_tf32(acc[nf][0], acc[nf][1], acc[nf][2], acc[nf][3],
                         ah0, ah1, ah2, ah3, bh0, bh1);
                mma_tf32(acc[nf][0], acc[nf][1], acc[nf][2], acc[nf][3],
                         ah0, ah1, ah2, ah3, bl0, bl1);
                mma_tf32(acc[nf][0], acc[nf][1], acc[nf][2], acc[nf][3],
                         al0, al1, al2, al3, bh0, bh1);
            }
        }
        __syncthreads();
    }

    const int row0 = m0 + mbase + lr4;
    if (Yred == nullptr) {
        const size_t pb0 = (size_t)kz * M_ROWS;
        #pragma unroll
        for (int nf = 0; nf < 4; nf++) {
            const int n = n0 + nbase + nf * 8 + lc4 * 2;
            *(float2*)&P[(pb0 + row0) * N + n]     = make_float2(acc[nf][0], acc[nf][1]);
            *(float2*)&P[(pb0 + row0 + 8) * N + n] = make_float2(acc[nf][2], acc[nf][3]);
        }
    } else {
        #pragma unroll
        for (int nf = 0; nf < 4; nf++) {
            const int n = n0 + nbase + nf * 8 + lc4 * 2;
            float v00 = acc[nf][0], v01 = acc[nf][1];
            float v10 = acc[nf][2], v11 = acc[nf][3];
            if (kz == 0) {
                float2 bb2 = *(const float2*)&bias[n];
                v00 += bb2.x; v01 += bb2.y;
                v10 += bb2.x; v11 += bb2.y;
            }
            atomicAdd(&Yred[(size_t)row0 * N + n],       v00);
            atomicAdd(&Yred[(size_t)row0 * N + n + 1],   v01);
            atomicAdd(&Yred[(size_t)(row0 + 8) * N + n],     v10);
            atomicAdd(&Yred[(size_t)(row0 + 8) * N + n + 1], v11);
        }
    }
}

// ---------------------------------------------------------------------------
// Fused attention + cache copy-out, split-KV x16, 3xTF32 tensor cores,
// cp.async double-buffered 32-row tiles, warp-specialized copy-out.
// q reduced from 4 QKV split-K partials + bias in-kernel; split-15 blocks
// materialize the 16 new K/V rows from partials before staging reaches them.
// ---------------------------------------------------------------------------
__global__ __launch_bounds__(256)
void attn_split_kernel(const float* __restrict__ cache_k,
                       const float* __restrict__ cache_v,
                       float* __restrict__ out_k,
                       float* __restrict__ out_v,
                       const float* __restrict__ qkv_b) {
    __shared__ unsigned qh[16][68];
    __shared__ unsigned ql[16][68];
    __shared__ __align__(16) float kt[2][TILE][68];
    __shared__ __align__(16) float vt[2][TILE][68];
    __shared__ float ptT[16][36];
    __shared__ float m_run[16], l_run[16], fac_s[16];

    const int tid   = threadIdx.x;
    const int bh    = blockIdx.x >> 4;
    const int split = blockIdx.x & 15;
    const int b = bh >> 4, h = bh & 15;

    const int w   = tid >> 5;
    const int L   = tid & 31;
    const int lr4 = L >> 2;
    const int lc4 = L & 3;

    const size_t cbase = (size_t)bh * (PAST * 64);
    const size_t obase = (size_t)bh * (L_TOT * 64);

    // ---- q = sum of 4 split-K partials + bias, scaled, hi/lo split ----
    {
        const int q = tid >> 4, c4 = tid & 15;
        const size_t qoff = (size_t)(b * 16 + q) * 3072 + h * 64 + c4 * 4;
        float4 qv = *(const float4*)&g_part[qoff];
        #pragma unroll
        for (int kz = 1; kz < KSPLIT; kz++) {
            float4 p = *(const float4*)&g_part[(size_t)kz * (M_ROWS * 3072) + qoff];
            qv.x += p.x; qv.y += p.y; qv.z += p.z; qv.w += p.w;
        }
        float4 bb = *(const float4*)&qkv_b[h * 64 + c4 * 4];
        qv.x = (qv.x + bb.x) * 0.125f;
        qv.y = (qv.y + bb.y) * 0.125f;
        qv.z = (qv.z + bb.z) * 0.125f;
        qv.w = (qv.w + bb.w) * 0.125f;
        unsigned hi, lo;
        tf_split(qv.x, hi, lo); qh[q][c4 * 4 + 0] = hi; ql[q][c4 * 4 + 0] = lo;
        tf_split(qv.y, hi, lo); qh[q][c4 * 4 + 1] = hi; ql[q][c4 * 4 + 1] = lo;
        tf_split(qv.z, hi, lo); qh[q][c4 * 4 + 2] = hi; ql[q][c4 * 4 + 2] = lo;
        tf_split(qv.w, hi, lo); qh[q][c4 * 4 + 3] = hi; ql[q][c4 * 4 + 3] = lo;
    }

    // ---- split 15: materialize new K/V tail rows from partials ----
    if (split == 15) {
        const int s = tid >> 4, d4 = tid & 15;
        const size_t rbase = (size_t)(b * 16 + s) * 3072 + h * 64 + d4 * 4;
        float4 kv = *(const float4*)&g_part[rbase + 1024];
        float4 vv = *(const float4*)&g_part[rbase + 2048];
        #pragma unroll
        for (int kz = 1; kz < KSPLIT; kz++) {
            const size_t off = (size_t)kz * (M_ROWS * 3072) + rbase;
            float4 pk = *(const float4*)&g_part[off + 1024];
            float4 pv = *(const float4*)&g_part[off + 2048];
            kv.x += pk.x; kv.y += pk.y; kv.z += pk.z; kv.w += pk.w;
            vv.x += pv.x; vv.y += pv.y; vv.z += pv.z; vv.w += pv.w;
        }
        float4 bk = *(const float4*)&qkv_b[1024 + h * 64 + d4 * 4];
        float4 bv = *(const float4*)&qkv_b[2048 + h * 64 + d4 * 4];
        kv.x += bk.x; kv.y += bk.y; kv.z += bk.z; kv.w += bk.w;
        vv.x += bv.x; vv.y += bv.y; vv.z += bv.z; vv.w += bv.w;
        const size_t doff = obase + (size_t)(PAST + s) * 64 + d4 * 4;
        *(float4*)&out_k[doff] = kv;
        *(float4*)&out_v[doff] = vv;
    }
    if (tid < 16) { m_run[tid] = -1e30f; l_run[tid] = 0.0f; }
    __syncthreads();   // tail rows + q visible before any staging reads them

    const int chunk0 = split * 256;
    const int nrows  = (split == 15) ? 272 : 256;
    const int ntiles = (split == 15) ? 9 : 8;

    const int sr = tid >> 4;
    const int sc = tid & 15;

    const int pq = tid >> 4;
    const int dc = tid & 15;

    float oc0 = 0.f, oc1 = 0.f, oc2 = 0.f, oc3 = 0.f;

    auto stage = [&](int t, int bb) {
        const int l0 = chunk0 + t * TILE;
        const int rows = min(TILE, chunk0 + nrows - l0);
        #pragma unroll
        for (int i = 0; i < 2; i++) {
            const int r = sr + i * 16;
            if (r < rows) {
                const int gl = l0 + r;
                const size_t off = (size_t)gl * 64 + sc * 4;
                const float* ksrc = (gl < PAST) ? (cache_k + cbase + off)
                                                : (out_k + obase + off);
                const float* vsrc = (gl < PAST) ? (cache_v + cbase + off)
                                                : (out_v + obase + off);
                CP_ASYNC16(smem_u32(&kt[bb][r][sc * 4]), ksrc);
                CP_ASYNC16(smem_u32(&vt[bb][r][sc * 4]), vsrc);
            }
        }
    };

    stage(0, 0);
    CP_COMMIT();

    for (int t = 0; t < ntiles; t++) {
        const int bb   = t & 1;
        const int l0   = chunk0 + t * TILE;
        const int rows = min(TILE, chunk0 + nrows - l0);

        __syncthreads();

        if (t + 1 < ntiles) {
            stage(t + 1, bb ^ 1);
            CP_COMMIT();
            CP_WAIT1();
        } else {
            CP_WAIT0();
        }
        __syncthreads();

        if (w < 4) {
            float c0 = 0.f, c1 = 0.f, c2 = 0.f, c3 = 0.f;
            #pragma unroll
            for (int ks = 0; ks < 8; ks++) {
                const int k0 = ks * 8;
                unsigned ah0 = qh[lr4    ][k0 + lc4];
                unsigned ah1 = qh[lr4 + 8][k0 + lc4];
                unsigned ah2 = qh[lr4    ][k0 + 4 + lc4];
                unsigned ah3 = qh[lr4 + 8][k0 + 4 + lc4];
                unsigned al0 = ql[lr4    ][k0 + lc4];
                unsigned al1 = ql[lr4 + 8][k0 + lc4];
                unsigned al2 = ql[lr4    ][k0 + 4 + lc4];
                unsigned al3 = ql[lr4 + 8][k0 + 4 + lc4];
                float b0f = kt[bb][w * 8 + lr4][k0 + lc4];
                float b1f = kt[bb][w * 8 + lr4][k0 + 4 + lc4];
                unsigned bh0, bl0, bh1, bl1;
                tf_split(b0f, bh0, bl0);
                tf_split(b1f, bh1, bl1);
                mma_tf32(c0, c1, c2, c3, ah0, ah1, ah2, ah3, bh0, bh1);
                mma_tf32(c0, c1, c2, c3, ah0, ah1, ah2, ah3, bl0, bl1);
                mma_tf32(c0, c1, c2, c3, al0, al1, al2, al3, bh0, bh1);
            }
            const int n = w * 8 + lc4 * 2;
            ptT[lr4    ][n    ] = (n     < rows) ? c0 : -1e30f;
            ptT[lr4    ][n + 1] = (n + 1 < rows) ? c1 : -1e30f;
            ptT[lr4 + 8][n    ] = (n     < rows) ? c2 : -1e30f;
            ptT[lr4 + 8][n + 1] = (n + 1 < rows) ? c3 : -1e30f;
        } else {
            const int wtid = tid - 128;
            const int cr = wtid >> 4;
            const int cc = wtid & 15;
            #pragma unroll
            for (int j = 0; j < 4; j++) {
                const int r = cr + j * 8;
                const int gl = l0 + r;
                if (r < rows && gl < PAST) {
                    const size_t off = (size_t)gl * 64 + cc * 4;
                    *(float4*)&out_k[obase + off] = *(const float4*)&kt[bb][r][cc * 4];
                    *(float4*)&out_v[obase + off] = *(const float4*)&vt[bb][r][cc * 4];
                }
            }
        }
        __syncthreads();

        {
            float2 p = *(const float2*)&ptT[pq][dc * 2];
            float mt = fmaxf(p.x, p.y);
            #pragma unroll
            for (int s = 8; s >= 1; s >>= 1)
                mt = fmaxf(mt, __shfl_xor_sync(0xffffffffu, mt, s, 16));
            const float mo = m_run[pq];
            const float mn = fmaxf(mo, mt);
            const float fc = __expf(mo - mn);
            p.x = __expf(p.x - mn);
            p.y = __expf(p.y - mn);
            *(float2*)&ptT[pq][dc * 2] = p;
            float ss = p.x + p.y;
            #pragma unroll
            for (int s = 8; s >= 1; s >>= 1)
                ss += __shfl_xor_sync(0xffffffffu, ss, s, 16);
            if (dc == 0) {
                m_run[pq] = mn;
                fac_s[pq] = fc;
                l_run[pq] = l_run[pq] * fc + ss;
            }
        }
        __syncthreads();

        {
            const float f0 = fac_s[lr4];
            const float f1 = fac_s[lr4 + 8];
            oc0 *= f0; oc1 *= f0; oc2 *= f1; oc3 *= f1;

            #pragma unroll
            for (int ks = 0; ks < 4; ks++) {
                const int k0 = ks * 8;
                float af0 = ptT[lr4    ][k0 + lc4];
                float af1 = ptT[lr4 + 8][k0 + lc4];
                float af2 = ptT[lr4    ][k0 + 4 + lc4];
                float af3 = ptT[lr4 + 8][k0 + 4 + lc4];
                unsigned ah0, al0, ah1, al1, ah2, al2, ah3, al3;
                tf_split(af0, ah0, al0);
                tf_split(af1, ah1, al1);
                tf_split(af2, ah2, al2);
                tf_split(af3, ah3, al3);
                float b0f = vt[bb][k0 + lc4    ][w * 8 + lr4];
                float b1f = vt[bb][k0 + 4 + lc4][w * 8 + lr4];
                unsigned bh0, bl0, bh1, bl1;
                tf_split(b0f, bh0, bl0);
                tf_split(b1f, bh1, bl1);
                mma_tf32(oc0, oc1, oc2, oc3, ah0, ah1, ah2, ah3, bh0, bh1);
                mma_tf32(oc0, oc1, oc2, oc3, ah0, ah1, ah2, ah3, bl0, bl1);
                mma_tf32(oc0, oc1, oc2, oc3, al0, al1, al2, al3, bh0, bh1);
            }
        }
    }

    {
        const size_t pbase = (size_t)blockIdx.x * 1024;
        const int d = w * 8 + lc4 * 2;
        *(float2*)&g_po[pbase + lr4       * 64 + d] = make_float2(oc0, oc1);
        *(float2*)&g_po[pbase + (lr4 + 8) * 64 + d] = make_float2(oc2, oc3);
    }
    if (tid < 16) {
        g_pm[blockIdx.x * 16 + tid] = m_run[tid];
        g_pl[blockIdx.x * 16 + tid] = l_run[tid];
    }
}

// ---------------------------------------------------------------------------
// Combine split partials -> g_obuf; also zero out_y for the y-GEMM RED.
// ---------------------------------------------------------------------------
__global__ __launch_bounds__(256)
void attn_reduce_kernel(float* __restrict__ Y) {
    const int bh = blockIdx.x;
    const int tid = threadIdx.x;
    const int pq = tid >> 4, dc = tid & 15;
    const int base = bh * NSPLIT;

    // zero out_y: 256 blocks x 256 threads x one float4 = 262144 floats
    {
        const unsigned idx = blockIdx.x * 256u + tid;
        *(float4*)&Y[idx * 4] = make_float4(0.f, 0.f, 0.f, 0.f);
    }

    float mm = -1e30f;
    #pragma unroll
    for (int s = 0; s < NSPLIT; s++)
        mm = fmaxf(mm, g_pm[(base + s) * 16 + pq]);

    float4 acc = make_float4(0.f, 0.f, 0.f, 0.f);
    float l = 0.f;
    #pragma unroll
    for (int s = 0; s < NSPLIT; s++) {
        float w = __expf(g_pm[(base + s) * 16 + pq] - mm);
        float4 o = *(const float4*)&g_po[(size_t)(base + s) * 1024 + pq * 64 + dc * 4];
        acc.x += w * o.x; acc.y += w * o.y;
        acc.z += w * o.z; acc.w += w * o.w;
        l += w * g_pl[(base + s) * 16 + pq];
    }
    float inv = 1.0f / l;
    const int b = bh >> 4, h = bh & 15;
    float4 r = make_float4(acc.x * inv, acc.y * inv, acc.z * inv, acc.w * inv);
    *(float4*)&g_obuf[(size_t)(b * 16 + pq) * D_MODEL + h * 64 + dc * 4] = r;
}

// ---------------------------------------------------------------------------
extern "C" void kernel_launch(void* const* d_in, const int* in_sizes, int n_in,
                              void* d_out, int out_size) {
    const float* x       = (const float*)d_in[0];
    const float* cache_k = (const float*)d_in[1];
    const float* cache_v = (const float*)d_in[2];
    const float* qkv_w   = (const float*)d_in[3];
    const float* qkv_b   = (const float*)d_in[4];
    const float* out_w   = (const float*)d_in[5];
    const float* out_b   = (const float*)d_in[6];

    float* out   = (float*)d_out;
    float* out_y = out + OUT_Y_OFF;
    float* out_k = out + OUT_K_OFF;
    float* out_v = out + OUT_V_OFF;

    float *obuf_p = nullptr, *part_p = nullptr;
    cudaGetSymbolAddress((void**)&obuf_p, g_obuf);
    cudaGetSymbolAddress((void**)&part_p, g_part);

    // 1) QKV projection, split-K x4 -> partials (consumed directly by attn)
    gemm_tf32_split_kernel<<<dim3(3072 / 64, M_ROWS / 64, KSPLIT), 256>>>(
        x, qkv_w, part_p, 3072, D_MODEL, nullptr, nullptr);

    // 2) Fused attention + cache copy-out; q and new-KV tail reduced in-kernel
    attn_split_kernel<<<B_SZ * H_SZ * NSPLIT, 256>>>(
        cache_k, cache_v, out_k, out_v, qkv_b);

    // 3) Combine splits -> g_obuf; zero out_y
    attn_reduce_kernel<<<B_SZ * H_SZ, 256>>>(out_y);

    // 4) Output projection, split-K x8, RED directly into out_y (+bias)
    gemm_tf32_split_kernel<<<dim3(D_MODEL / 64, M_ROWS / 64, KSPLIT_Y), 256>>>(
        obuf_p, out_w, nullptr, D_MODEL, D_MODEL, out_y, out_b);
}